// round 1
// baseline (speedup 1.0000x reference)
#include <cuda_runtime.h>

// LIF recurrence: B=64, T=1000, H=512, fp32.
// One thread per (b, h) neuron; sequential scan over T.
// Warp lanes span consecutive h -> coalesced 128B load + 128B store per warp per t.
// Time loop unrolled by 8 so ptxas front-batches 8 independent LDGs (MLP=8).

#define LIF_B 64
#define LIF_T 1000
#define LIF_H 512
#define LIF_UNROLL 8

__global__ __launch_bounds__(128, 8) void LIF_30554397344397_kernel(
    const float* __restrict__ x,       // (B, T, H)
    const float* __restrict__ dc,      // (2,)  [alpha, beta] before clamping
    const float* __restrict__ thp,     // ()    threshold
    float* __restrict__ out)           // (B, T, H) spikes
{
    const int idx = blockIdx.x * 128 + threadIdx.x;   // 0 .. B*H-1
    const int b = idx >> 9;        // / 512
    const int h = idx & (LIF_H - 1);

    const float alpha = fminf(fmaxf(dc[0], 0.5f), 1.0f);
    const float beta  = fminf(fmaxf(dc[1], 0.5f), 1.0f);
    const float th    = thp[0];
    const float a1 = 1.0f - alpha;
    const float b1 = 1.0f - beta;

    const float* xp = x   + (size_t)b * (LIF_T * LIF_H) + h;
    float*       op = out + (size_t)b * (LIF_T * LIF_H) + h;

    float mem = 0.0f, syn = 0.0f, spike = 0.0f;

    for (int tc = 0; tc < LIF_T; tc += LIF_UNROLL) {
        // Front-batched independent loads for this time-chunk (MLP = 8).
        float xv[LIF_UNROLL];
        #pragma unroll
        for (int u = 0; u < LIF_UNROLL; u++) {
            xv[u] = xp[u * LIF_H];
        }

        // Serial LIF steps for the chunk.
        #pragma unroll
        for (int u = 0; u < LIF_UNROLL; u++) {
            // reset (stop_gradient irrelevant in forward): mem -= mem * spike
            float memr = mem - mem * spike;
            // membrane update uses OLD syn
            mem = alpha * memr + a1 * syn;
            // synaptic update
            syn = beta * syn + b1 * xv[u];
            // heaviside(mem - th, 1.0): 1 for (mem - th) >= 0
            spike = (mem >= th) ? 1.0f : 0.0f;
            op[u * LIF_H] = spike;
        }

        xp += LIF_UNROLL * LIF_H;
        op += LIF_UNROLL * LIF_H;
    }
}

extern "C" void kernel_launch(void* const* d_in, const int* in_sizes, int n_in,
                              void* d_out, int out_size) {
    const float* x   = (const float*)d_in[0];  // (B, T, H) float32
    const float* dc  = (const float*)d_in[1];  // (2,) float32
    const float* thp = (const float*)d_in[2];  // scalar float32
    float* out = (float*)d_out;                // (B, T, H) float32

    const int total_threads = LIF_B * LIF_H;   // 32768
    const int block = 128;
    const int grid = total_threads / block;    // 256

    LIF_30554397344397_kernel<<<grid, block>>>(x, dc, thp, out);
}

// round 2
// speedup vs baseline: 1.0226x; 1.0226x over previous
#include <cuda_runtime.h>

// LIF recurrence: B=64, T=1000, H=512, fp32.
// One thread per (b, h) neuron; sequential scan over T.
// Unroll=20 so each warp keeps 20 coalesced 128B loads in flight
// (2.5KB/warp x 1024 warps ~= 2.6MB chip-wide = HBM BW-latency product).

#define LIF_B 64
#define LIF_T 1000
#define LIF_H 512
#define LIF_UNROLL 20
#define LIF_BLOCK 64

__global__ __launch_bounds__(LIF_BLOCK) void LIF_30554397344397_kernel(
    const float* __restrict__ x,       // (B, T, H)
    const float* __restrict__ dc,      // (2,)  [alpha, beta] before clamping
    const float* __restrict__ thp,     // ()    threshold
    float* __restrict__ out)           // (B, T, H) spikes
{
    const int idx = blockIdx.x * LIF_BLOCK + threadIdx.x;   // 0 .. B*H-1
    const int b = idx >> 9;        // / 512
    const int h = idx & (LIF_H - 1);

    const float alpha = fminf(fmaxf(dc[0], 0.5f), 1.0f);
    const float beta  = fminf(fmaxf(dc[1], 0.5f), 1.0f);
    const float th    = thp[0];
    const float a1 = 1.0f - alpha;
    const float b1 = 1.0f - beta;

    const float* xp = x   + (size_t)b * (LIF_T * LIF_H) + h;
    float*       op = out + (size_t)b * (LIF_T * LIF_H) + h;

    float mem = 0.0f, syn = 0.0f;
    bool  spiked = false;

    for (int tc = 0; tc < LIF_T; tc += LIF_UNROLL) {
        // Front-batched independent streaming loads (MLP = 20).
        float xv[LIF_UNROLL];
        #pragma unroll
        for (int u = 0; u < LIF_UNROLL; u++) {
            xv[u] = __ldcs(xp + u * LIF_H);
        }

        // Serial LIF steps for the chunk.
        #pragma unroll
        for (int u = 0; u < LIF_UNROLL; u++) {
            // reset: mem -= mem*spike, spike in {0,1} -> select
            float memr = spiked ? 0.0f : mem;
            // membrane update uses OLD syn; a1*syn off the critical path
            mem = fmaf(alpha, memr, a1 * syn);
            // synaptic update (independent of mem chain)
            syn = fmaf(b1, xv[u], beta * syn);
            // heaviside(mem - th, 1.0): 1 for mem >= th
            spiked = (mem >= th);
            __stcs(op + u * LIF_H, spiked ? 1.0f : 0.0f);
        }

        xp += LIF_UNROLL * LIF_H;
        op += LIF_UNROLL * LIF_H;
    }
}

extern "C" void kernel_launch(void* const* d_in, const int* in_sizes, int n_in,
                              void* d_out, int out_size) {
    const float* x   = (const float*)d_in[0];  // (B, T, H) float32
    const float* dc  = (const float*)d_in[1];  // (2,) float32
    const float* thp = (const float*)d_in[2];  // scalar float32
    float* out = (float*)d_out;                // (B, T, H) float32

    const int total_threads = LIF_B * LIF_H;   // 32768
    const int grid = total_threads / LIF_BLOCK; // 512

    LIF_30554397344397_kernel<<<grid, LIF_BLOCK>>>(x, dc, thp, out);
}

// round 3
// speedup vs baseline: 1.2004x; 1.1739x over previous
#include <cuda_runtime.h>

// LIF recurrence: B=64, T=1000, H=512, fp32.
// One thread per (b, h) neuron; sequential scan over T.
// Double-buffered prefetch (U=20): loads for chunk c+1 are issued before the
// compute of chunk c, forcing 20 live load-dest registers per thread ->
// 1024 warps x 20 x 128B = 2.6MB in flight = HBM BW-latency product.

#define LIF_B 64
#define LIF_T 1000
#define LIF_H 512
#define LIF_U 20          // chunk size; 1000 = 50 * 20
#define LIF_BLOCK 64

__global__ __launch_bounds__(LIF_BLOCK, 1) void LIF_30554397344397_kernel(
    const float* __restrict__ x,       // (B, T, H)
    const float* __restrict__ dc,      // (2,)  [alpha, beta] before clamping
    const float* __restrict__ thp,     // ()    threshold
    float* __restrict__ out)           // (B, T, H) spikes
{
    const int idx = blockIdx.x * LIF_BLOCK + threadIdx.x;   // 0 .. B*H-1
    const int b = idx >> 9;        // / 512
    const int h = idx & (LIF_H - 1);

    const float alpha = fminf(fmaxf(dc[0], 0.5f), 1.0f);
    const float beta  = fminf(fmaxf(dc[1], 0.5f), 1.0f);
    const float th    = thp[0];
    const float a1 = 1.0f - alpha;
    const float b1 = 1.0f - beta;

    const float* xp = x   + (size_t)b * (LIF_T * LIF_H) + h;
    float*       op = out + (size_t)b * (LIF_T * LIF_H) + h;

    float mem = 0.0f, syn = 0.0f;
    bool  spiked = false;

    float va[LIF_U], vb[LIF_U];   // static double buffers (must stay in regs)

    // Prologue: prefetch chunk 0 into va.
    #pragma unroll
    for (int u = 0; u < LIF_U; u++) va[u] = __ldcs(xp + u * LIF_H);

    // 50 chunks, processed two per iteration so buffer roles are static.
    for (int c = 0; c < 50; c += 2) {
        const float* xpn = xp + LIF_U * LIF_H;

        // Prefetch chunk c+1 into vb (c+1 <= 49 always, since 50 is even).
        #pragma unroll
        for (int u = 0; u < LIF_U; u++) vb[u] = __ldcs(xpn + u * LIF_H);

        // Compute chunk c from va while vb loads are in flight.
        #pragma unroll
        for (int u = 0; u < LIF_U; u++) {
            float memr = spiked ? 0.0f : mem;
            mem = fmaf(alpha, memr, a1 * syn);
            syn = fmaf(b1, va[u], beta * syn);
            spiked = (mem >= th);
            __stcs(op + u * LIF_H, spiked ? 1.0f : 0.0f);
        }
        xp += 2 * LIF_U * LIF_H;
        op += LIF_U * LIF_H;

        // Prefetch chunk c+2 into va (skip on last iteration).
        if (c + 2 < 50) {
            #pragma unroll
            for (int u = 0; u < LIF_U; u++) va[u] = __ldcs(xp + u * LIF_H);
        }

        // Compute chunk c+1 from vb.
        #pragma unroll
        for (int u = 0; u < LIF_U; u++) {
            float memr = spiked ? 0.0f : mem;
            mem = fmaf(alpha, memr, a1 * syn);
            syn = fmaf(b1, vb[u], beta * syn);
            spiked = (mem >= th);
            __stcs(op + u * LIF_H, spiked ? 1.0f : 0.0f);
        }
        op += LIF_U * LIF_H;
    }
}

extern "C" void kernel_launch(void* const* d_in, const int* in_sizes, int n_in,
                              void* d_out, int out_size) {
    const float* x   = (const float*)d_in[0];  // (B, T, H) float32
    const float* dc  = (const float*)d_in[1];  // (2,) float32
    const float* thp = (const float*)d_in[2];  // scalar float32
    float* out = (float*)d_out;                // (B, T, H) float32

    const int total_threads = LIF_B * LIF_H;    // 32768
    const int grid = total_threads / LIF_BLOCK; // 512

    LIF_30554397344397_kernel<<<grid, LIF_BLOCK>>>(x, dc, thp, out);
}

// round 4
// speedup vs baseline: 1.2861x; 1.0714x over previous
#include <cuda_runtime.h>

// LIF recurrence: B=64, T=1000, H=512, fp32.
// One thread per (b, h) neuron; sequential scan over T.
// Double-buffered prefetch with U=50 (1000 = 20 chunks):
// each warp keeps ~50 outstanding LDGs (just under the ~55/warp HW cap)
// -> 1024 warps x 50 x 128B = 6.55MB in flight ~= loaded BW*latency product.

#define LIF_B 64
#define LIF_T 1000
#define LIF_H 512
#define LIF_U 50          // chunk size; 1000 = 20 * 50
#define LIF_BLOCK 64

__global__ __launch_bounds__(LIF_BLOCK, 4) void LIF_30554397344397_kernel(
    const float* __restrict__ x,       // (B, T, H)
    const float* __restrict__ dc,      // (2,)  [alpha, beta] before clamping
    const float* __restrict__ thp,     // ()    threshold
    float* __restrict__ out)           // (B, T, H) spikes
{
    const int idx = blockIdx.x * LIF_BLOCK + threadIdx.x;   // 0 .. B*H-1
    const int b = idx >> 9;        // / 512
    const int h = idx & (LIF_H - 1);

    const float alpha = fminf(fmaxf(dc[0], 0.5f), 1.0f);
    const float beta  = fminf(fmaxf(dc[1], 0.5f), 1.0f);
    const float th    = thp[0];
    const float a1 = 1.0f - alpha;
    const float b1 = 1.0f - beta;

    const float* xp = x   + (size_t)b * (LIF_T * LIF_H) + h;
    float*       op = out + (size_t)b * (LIF_T * LIF_H) + h;

    float mem = 0.0f, syn = 0.0f;
    bool  spiked = false;

    float va[LIF_U], vb[LIF_U];   // static double buffers (stay in regs)

    // Prologue: prefetch chunk 0 into va.
    #pragma unroll
    for (int u = 0; u < LIF_U; u++) va[u] = __ldcs(xp + u * LIF_H);

    // 20 chunks, two per iteration so buffer roles are static.
    for (int c = 0; c < 20; c += 2) {
        const float* xpn = xp + LIF_U * LIF_H;

        // Prefetch chunk c+1 into vb (always exists: 20 is even).
        #pragma unroll
        for (int u = 0; u < LIF_U; u++) vb[u] = __ldcs(xpn + u * LIF_H);

        // Compute chunk c from va while vb loads are in flight.
        #pragma unroll
        for (int u = 0; u < LIF_U; u++) {
            float memr = spiked ? 0.0f : mem;
            mem = fmaf(alpha, memr, a1 * syn);
            syn = fmaf(b1, va[u], beta * syn);
            spiked = (mem >= th);
            __stcs(op + u * LIF_H, spiked ? 1.0f : 0.0f);
        }
        xp += 2 * LIF_U * LIF_H;
        op += LIF_U * LIF_H;

        // Prefetch chunk c+2 into va (skip on the last iteration).
        if (c + 2 < 20) {
            #pragma unroll
            for (int u = 0; u < LIF_U; u++) va[u] = __ldcs(xp + u * LIF_H);
        }

        // Compute chunk c+1 from vb.
        #pragma unroll
        for (int u = 0; u < LIF_U; u++) {
            float memr = spiked ? 0.0f : mem;
            mem = fmaf(alpha, memr, a1 * syn);
            syn = fmaf(b1, vb[u], beta * syn);
            spiked = (mem >= th);
            __stcs(op + u * LIF_H, spiked ? 1.0f : 0.0f);
        }
        op += LIF_U * LIF_H;
    }
}

extern "C" void kernel_launch(void* const* d_in, const int* in_sizes, int n_in,
                              void* d_out, int out_size) {
    const float* x   = (const float*)d_in[0];  // (B, T, H) float32
    const float* dc  = (const float*)d_in[1];  // (2,) float32
    const float* thp = (const float*)d_in[2];  // scalar float32
    float* out = (float*)d_out;                // (B, T, H) float32

    const int total_threads = LIF_B * LIF_H;    // 32768
    const int grid = total_threads / LIF_BLOCK; // 512

    LIF_30554397344397_kernel<<<grid, LIF_BLOCK>>>(x, dc, thp, out);
}